// round 8
// baseline (speedup 1.0000x reference)
#include <cuda_runtime.h>
#include <cstdint>

// Problem constants
#define NB   32
#define NS   128
#define NW   4096      // NB*NS independent words
#define CC   32        // chars per word (time steps)
#define HH   256       // hidden
#define G3   768       // 3*H
#define EE   128       // embed dim
#define NV   262       // vocab
#define WPB  16        // words per block
#define HROW 20        // padded smem row for h (16 words + pad, 16B aligned)
#define BLOCKS_PER_DIR (NW / WPB)   // 256

typedef unsigned long long u64;

// Precomputed x-projection table: P[d][v][j] = embed[v].W_ih[d][j] + b_ih[d][j]
// (+ b_hh[j] folded in for the r and z gates, j < 512)
__device__ float g_P[2][NV][G3];
// k-major transposed recurrent weights: g_Wt[d][k][j] = W_hh[d][j][k]
__device__ float g_Wt[2][HH][G3];
// k-major transposed input weights (for coalesced prep_p)
__device__ float g_WtI[2][EE][G3];
// k-quad packed recurrent weights (NOT duplicated — same bytes as g_Wt):
// g_W4[d][k4][g][j] = (w_k, w_k+1, w_k+2, w_k+3) for k = 4*k4, gate g, col j
__device__ float4 g_W4[2][HH / 4][3][256];

// ---------------------------------------------------------------------------
// Packed fp32x2 helpers (Blackwell 2x-rate fp32; ptxas never auto-emits)
// ---------------------------------------------------------------------------
__device__ __forceinline__ void fma2(u64& d, u64 a, u64 b) {
    asm("fma.rn.f32x2 %0, %1, %2, %3;" : "=l"(d) : "l"(a), "l"(b), "l"(d));
}
__device__ __forceinline__ u64 dup2(float x) {
    u64 r;
    asm("mov.b64 %0, {%1, %1};" : "=l"(r) : "f"(x));
    return r;
}

// ---------------------------------------------------------------------------
// Prepack 0: transpose W_hh (768x256) and W_ih (768x128) to k-major.
// ---------------------------------------------------------------------------
__global__ void prep_tr_kernel(const float* __restrict__ Whh_fw,
                               const float* __restrict__ Whh_bw,
                               const float* __restrict__ Wih_fw,
                               const float* __restrict__ Wih_bw)
{
    int j = blockIdx.x;
    int d = blockIdx.y;
    int k = threadIdx.x;
    const float* Wh = d ? Whh_bw : Whh_fw;
    const float* Wi = d ? Wih_bw : Wih_fw;
    g_Wt[d][k][j] = Wh[(size_t)j * HH + k];
    if (k < EE) g_WtI[d][k][j] = Wi[(size_t)j * EE + k];
}

// ---------------------------------------------------------------------------
// Prepack 1: k-quad packed weight table (from g_Wt, coalesced reads).
// grid (HH/4, 2), 256 threads.
// ---------------------------------------------------------------------------
__global__ void prep_w4_kernel()
{
    int k4  = blockIdx.x;
    int d   = blockIdx.y;
    int tid = threadIdx.x;
#pragma unroll
    for (int g = 0; g < 3; g++) {
        float a = g_Wt[d][4 * k4 + 0][g * 256 + tid];
        float b = g_Wt[d][4 * k4 + 1][g * 256 + tid];
        float c = g_Wt[d][4 * k4 + 2][g * 256 + tid];
        float e = g_Wt[d][4 * k4 + 3][g * 256 + tid];
        g_W4[d][k4][g][tid] = make_float4(a, b, c, e);
    }
}

// ---------------------------------------------------------------------------
// Prepack 2: input-projection table, coalesced via g_WtI.  grid (NV, 2).
// ---------------------------------------------------------------------------
__global__ void prep_p_kernel(const float* __restrict__ embed,
                              const float* __restrict__ bih_fw,
                              const float* __restrict__ bhh_fw,
                              const float* __restrict__ bih_bw,
                              const float* __restrict__ bhh_bw)
{
    int v = blockIdx.x;
    int d = blockIdx.y;
    int tid = threadIdx.x;
    const float* bi = d ? bih_bw : bih_fw;
    const float* bh = d ? bhh_bw : bhh_fw;
    const float* ev = embed + (size_t)v * EE;
    float a0 = 0.f, a1 = 0.f, a2 = 0.f;
#pragma unroll 4
    for (int k = 0; k < EE; k++) {
        float e = __ldg(ev + k);                        // warp-broadcast
        const float* w = &g_WtI[d][k][0];
        a0 = fmaf(e, __ldg(w + tid),       a0);
        a1 = fmaf(e, __ldg(w + tid + 256), a1);
        a2 = fmaf(e, __ldg(w + tid + 512), a2);
    }
    g_P[d][v][tid]       = a0 + bi[tid]       + bh[tid];
    g_P[d][v][tid + 256] = a1 + bi[tid + 256] + bh[tid + 256];
    g_P[d][v][tid + 512] = a2 + bi[tid + 512];          // n-gate: b_hh NOT folded
}

// ---------------------------------------------------------------------------
// Activations
// ---------------------------------------------------------------------------
__device__ __forceinline__ float sigmoid_f(float x) {
    return __fdividef(1.f, 1.f + __expf(-x));
}
__device__ __forceinline__ float tanh_f(float x) {
    x = fmaxf(-15.f, fminf(15.f, x));
    float e = __expf(-2.f * x);
    return __fdividef(1.f - e, 1.f + e);
}

// ---------------------------------------------------------------------------
// Main recurrent kernel (packed fp32x2, 3 CTAs/SM).
// Block = 16 words x one direction, 256 threads; thread tid owns the (r,z,n)
// gate triple for hidden index i = tid.  Words packed in pairs into the
// f32x2 lanes; h stored word-major per k (hsm[k][word], row padded to 20)
// so one broadcast LDS.128 feeds two word-pair FFMA2s.  Weights: 3 LDG.128
// per 4k from the k-quad table (same bytes/wavefronts as 12 LDG.32, fewer
// issue slots), software-prefetched one 4k-group ahead.  launch_bounds
// (256,3) caps regs ~80 -> 3 CTAs/SM: 6 warps/SMSP and 1.15 waves.
// ---------------------------------------------------------------------------
__global__ void __launch_bounds__(256, 3) gru_kernel(
    const int*   __restrict__ chars,       // [NW, CC]
    const int*   __restrict__ chars_mask,  // [NW, CC]
    const int*   __restrict__ data_mask,   // [NW]
    const float* __restrict__ bhh_fw,      // [G3]
    const float* __restrict__ bhh_bw,
    float*       __restrict__ out)         // [NW, 512]
{
    __shared__ float hsm[HH * HROW];       // h[k][word], 20KB

    const int tid = threadIdx.x;
    const int d   = blockIdx.y;
    const int n0  = blockIdx.x * WPB;

    // weight table for this direction: W4[k4*3*256 + g*256 + tid]
    const float4* __restrict__ W4 =
        reinterpret_cast<const float4*>(&g_W4[d][0][0][0]);
    const float bn = (d ? bhh_bw : bhh_fw)[tid + 512];  // n-gate bias

    // init h = 0
#pragma unroll
    for (int q = 0; q < HH * HROW / 256; q++)           // 20 stores/thread
        hsm[tid + q * 256] = 0.f;
    __syncthreads();

    for (int step = 0; step < CC; step++) {
        const int t = d ? (CC - 1 - step) : step;

        // accumulators: 8 word-pairs x 3 gates, packed fp32x2
        u64 accr[WPB / 2], accz[WPB / 2], accn[WPB / 2];
#pragma unroll
        for (int p = 0; p < WPB / 2; p++) { accr[p] = 0ull; accz[p] = 0ull; accn[p] = 0ull; }

        // ---- gh = h @ W_hh^T; 4 k per iter, weights prefetched 1 iter ahead
        float4 c0 = __ldg(W4 + 0 * 256 + tid);           // r-gate, k 0..3
        float4 c1 = __ldg(W4 + 1 * 256 + tid);           // z-gate
        float4 c2 = __ldg(W4 + 2 * 256 + tid);           // n-gate
#pragma unroll 2
        for (int kg = 0; kg < HH / 4; kg++) {
            const int kn = (kg + 1 < HH / 4) ? (kg + 1) : kg;
            float4 p0 = __ldg(W4 + (kn * 3 + 0) * 256 + tid);
            float4 p1 = __ldg(W4 + (kn * 3 + 1) * 256 + tid);
            float4 p2 = __ldg(W4 + (kn * 3 + 2) * 256 + tid);
#pragma unroll
            for (int i = 0; i < 4; i++) {
                const int k = 4 * kg + i;
                const float wr = (i == 0) ? c0.x : (i == 1) ? c0.y : (i == 2) ? c0.z : c0.w;
                const float wz = (i == 0) ? c1.x : (i == 1) ? c1.y : (i == 2) ? c1.z : c1.w;
                const float wn = (i == 0) ? c2.x : (i == 1) ? c2.y : (i == 2) ? c2.z : c2.w;
                const u64 wr2 = dup2(wr);
                const u64 wz2 = dup2(wz);
                const u64 wn2 = dup2(wn);
                const ulonglong2* __restrict__ hk =
                    reinterpret_cast<const ulonglong2*>(&hsm[k * HROW]);
#pragma unroll
                for (int q = 0; q < WPB / 4; q++) {      // 4 LDS.128 broadcast
                    ulonglong2 a = hk[q];                // words 4q..4q+3
                    fma2(accr[2 * q],     a.x, wr2);
                    fma2(accz[2 * q],     a.x, wz2);
                    fma2(accn[2 * q],     a.x, wn2);
                    fma2(accr[2 * q + 1], a.y, wr2);
                    fma2(accz[2 * q + 1], a.y, wz2);
                    fma2(accn[2 * q + 1], a.y, wn2);
                }
            }
            c0 = p0; c1 = p1; c2 = p2;
        }

        // ---- gates (thread-local), update h --------------------------------
        __syncthreads();                                 // all h reads done
        const float* ar = reinterpret_cast<const float*>(accr);
        const float* az = reinterpret_cast<const float*>(accz);
        const float* an = reinterpret_cast<const float*>(accn);
#pragma unroll
        for (int w = 0; w < WPB; w++) {
            const int n  = n0 + w;
            const int ch = chars[n * CC + t];
            const int mk = chars_mask[n * CC + t];
            const float* __restrict__ Prow = &g_P[d][ch][0];
            float xr = Prow[tid];                        // b_ih + b_hh folded
            float xz = Prow[tid + 256];
            float xn = Prow[tid + 512];                  // b_ih only
            float hold = hsm[tid * HROW + w];
            float r  = sigmoid_f(xr + ar[w]);
            float z  = sigmoid_f(xz + az[w]);
            float hn = bn + an[w];
            float nn = tanh_f(fmaf(r, hn, xn));
            float hnew = (1.f - z) * nn + z * hold;
            hsm[tid * HROW + w] = mk ? hnew : hold;      // freeze past seq end
        }
        __syncthreads();                                 // h visible next step
    }

    // ---- final write: out[n, d*256 + i] = h * data_mask[n] -----------------
#pragma unroll
    for (int w = 0; w < WPB; w++) {
        const int n = n0 + w;
        const float dm = data_mask[n] ? 1.f : 0.f;
        out[(size_t)n * 512 + d * 256 + tid] = hsm[tid * HROW + w] * dm;
    }
}

// ---------------------------------------------------------------------------
extern "C" void kernel_launch(void* const* d_in, const int* in_sizes, int n_in,
                              void* d_out, int out_size)
{
    const int*   chars      = (const int*)  d_in[0];
    const int*   chars_mask = (const int*)  d_in[1];
    const int*   data_mask  = (const int*)  d_in[2];
    const float* embed      = (const float*)d_in[3];
    const float* Wih_fw     = (const float*)d_in[4];
    const float* Whh_fw     = (const float*)d_in[5];
    const float* bih_fw     = (const float*)d_in[6];
    const float* bhh_fw     = (const float*)d_in[7];
    const float* Wih_bw     = (const float*)d_in[8];
    const float* Whh_bw     = (const float*)d_in[9];
    const float* bih_bw     = (const float*)d_in[10];
    const float* bhh_bw     = (const float*)d_in[11];
    float* out = (float*)d_out;

    prep_tr_kernel<<<dim3(G3, 2), HH>>>(Whh_fw, Whh_bw, Wih_fw, Wih_bw);
    prep_w4_kernel<<<dim3(HH / 4, 2), 256>>>();
    prep_p_kernel<<<dim3(NV, 2), 256>>>(embed, bih_fw, bhh_fw, bih_bw, bhh_bw);
    gru_kernel<<<dim3(BLOCKS_PER_DIR, 2), 256>>>(chars, chars_mask, data_mask,
                                                 bhh_fw, bhh_bw, out);
}

// round 9
// speedup vs baseline: 2.8537x; 2.8537x over previous
#include <cuda_runtime.h>
#include <cstdint>

// Problem constants
#define NB   32
#define NS   128
#define NW   4096      // NB*NS independent words
#define CC   32        // chars per word (time steps)
#define HH   256       // hidden
#define G3   768       // 3*H
#define EE   128       // embed dim
#define NV   262       // vocab
#define WPB  16        // words per block
#define HROW 20        // padded smem row for h (16 words + pad, 16B aligned)
#define NTILES (NW / WPB)           // 256

typedef unsigned long long u64;

// Precomputed x-projection table: P[d][v][j] = embed[v].W_ih[d][j] + b_ih[d][j]
// (+ b_hh[j] folded in for the r and z gates, j < 512)
__device__ float g_P[2][NV][G3];
// k-major transposed recurrent weights: g_Wt[d][k][j] = W_hh[d][j][k]
__device__ float g_Wt[2][HH][G3];
// k-major transposed input weights (for coalesced prep_p)
__device__ float g_WtI[2][EE][G3];
// length-sort structures
__device__ int g_len[NW];          // per-word char length
__device__ int g_perm[NW];         // word ids sorted by length DESCENDING
__device__ int g_bucket_pos[33];   // scatter cursors

// ---------------------------------------------------------------------------
// Packed fp32x2 helpers (Blackwell 2x-rate fp32; ptxas never auto-emits)
// ---------------------------------------------------------------------------
__device__ __forceinline__ void fma2(u64& d, u64 a, u64 b) {
    asm("fma.rn.f32x2 %0, %1, %2, %3;" : "=l"(d) : "l"(a), "l"(b), "l"(d));
}
__device__ __forceinline__ u64 dup2(float x) {
    u64 r;
    asm("mov.b64 %0, {%1, %1};" : "=l"(r) : "f"(x));
    return r;
}

// ---------------------------------------------------------------------------
// Prepack 0: transpose W_hh (768x256) and W_ih (768x128) to k-major.
// ---------------------------------------------------------------------------
__global__ void prep_tr_kernel(const float* __restrict__ Whh_fw,
                               const float* __restrict__ Whh_bw,
                               const float* __restrict__ Wih_fw,
                               const float* __restrict__ Wih_bw)
{
    int j = blockIdx.x;
    int d = blockIdx.y;
    int k = threadIdx.x;
    const float* Wh = d ? Whh_bw : Whh_fw;
    const float* Wi = d ? Wih_bw : Wih_fw;
    g_Wt[d][k][j] = Wh[(size_t)j * HH + k];
    if (k < EE) g_WtI[d][k][j] = Wi[(size_t)j * EE + k];
}

// ---------------------------------------------------------------------------
// Prepack 1: input-projection table, coalesced via g_WtI.  grid (NV, 2).
// ---------------------------------------------------------------------------
__global__ void prep_p_kernel(const float* __restrict__ embed,
                              const float* __restrict__ bih_fw,
                              const float* __restrict__ bhh_fw,
                              const float* __restrict__ bih_bw,
                              const float* __restrict__ bhh_bw)
{
    int v = blockIdx.x;
    int d = blockIdx.y;
    int tid = threadIdx.x;
    const float* bi = d ? bih_bw : bih_fw;
    const float* bh = d ? bhh_bw : bhh_fw;
    const float* ev = embed + (size_t)v * EE;
    float a0 = 0.f, a1 = 0.f, a2 = 0.f;
#pragma unroll 4
    for (int k = 0; k < EE; k++) {
        float e = __ldg(ev + k);                        // warp-broadcast
        const float* w = &g_WtI[d][k][0];
        a0 = fmaf(e, __ldg(w + tid),       a0);
        a1 = fmaf(e, __ldg(w + tid + 256), a1);
        a2 = fmaf(e, __ldg(w + tid + 512), a2);
    }
    g_P[d][v][tid]       = a0 + bi[tid]       + bh[tid];
    g_P[d][v][tid + 256] = a1 + bi[tid + 256] + bh[tid + 256];
    g_P[d][v][tid + 512] = a2 + bi[tid + 512];          // n-gate: b_hh NOT folded
}

// ---------------------------------------------------------------------------
// Prepack 2: counting sort of words by length, DESCENDING.
// chars_mask is a contiguous prefix -> len = popcount of the row.
// Single block, 1024 threads.  Scatter order within a length bucket is
// nondeterministic (atomics) but the kernel output is permutation-invariant:
// each word's computation and its out[] slot are independent of tile order.
// ---------------------------------------------------------------------------
__global__ void prep_sort_kernel(const int* __restrict__ chars_mask)
{
    __shared__ int hist[33];
    __shared__ int base[33];
    const int tid = threadIdx.x;
    if (tid < 33) hist[tid] = 0;
    __syncthreads();

    // lengths + histogram (bucket key = 32 - len so buckets run desc)
    int mylen[NW / 1024];
#pragma unroll
    for (int q = 0; q < NW / 1024; q++) {
        const int n = tid + q * 1024;
        const int* row = chars_mask + n * CC;
        int len = 0;
#pragma unroll
        for (int c = 0; c < CC; c++) len += row[c];
        mylen[q] = len;
        g_len[n] = len;
        atomicAdd(&hist[32 - len], 1);
    }
    __syncthreads();

    if (tid == 0) {                 // exclusive prefix over 33 bins
        int acc = 0;
        for (int b = 0; b < 33; b++) { base[b] = acc; acc += hist[b]; }
    }
    __syncthreads();
    if (tid < 33) g_bucket_pos[tid] = base[tid];
    __syncthreads();

#pragma unroll
    for (int q = 0; q < NW / 1024; q++) {
        const int n = tid + q * 1024;
        const int pos = atomicAdd(&g_bucket_pos[32 - mylen[q]], 1);
        g_perm[pos] = n;
    }
}

// ---------------------------------------------------------------------------
// Activations
// ---------------------------------------------------------------------------
__device__ __forceinline__ float sigmoid_f(float x) {
    return __fdividef(1.f, 1.f + __expf(-x));
}
__device__ __forceinline__ float tanh_f(float x) {
    x = fmaxf(-15.f, fminf(15.f, x));
    float e = __expf(-2.f * x);
    return __fdividef(1.f - e, 1.f + e);
}

// ---------------------------------------------------------------------------
// Main recurrent kernel (R3 hot loop + length-sorted tiles).
// Tile = 16 length-sorted words (descending), so the tile only runs
// maxlen = len(first word) steps instead of 32 (~1.9x less GEMV work).
// Forward: t = 0..maxlen-1 (steps beyond a word's len are frozen by mask).
// Backward: t = maxlen-1..0 (steps above maxlen would all be masked and
// leave h = 0, so skipping them is exact).
// ---------------------------------------------------------------------------
__global__ void __launch_bounds__(256, 2) gru_kernel(
    const int*   __restrict__ chars,       // [NW, CC]
    const int*   __restrict__ chars_mask,  // [NW, CC]
    const int*   __restrict__ data_mask,   // [NW]
    const float* __restrict__ bhh_fw,      // [G3]
    const float* __restrict__ bhh_bw,
    float*       __restrict__ out)         // [NW, 512]
{
    __shared__ float hsm[HH * HROW];       // h[k][word], 20KB
    __shared__ int   wid_s[WPB];           // real word ids of this tile

    const int tid  = threadIdx.x;
    const int d    = blockIdx.y;
    const int tile = blockIdx.x;

    const float* __restrict__ Wt = &g_Wt[d][0][0];      // [256][768]
    const float  bn = (d ? bhh_bw : bhh_fw)[tid + 512]; // n-gate bias

    if (tid < WPB) wid_s[tid] = g_perm[tile * WPB + tid];
    const int maxlen = g_len[g_perm[tile * WPB]];       // first = longest

    // init h = 0
#pragma unroll
    for (int q = 0; q < HH * HROW / 256; q++)           // 20 stores/thread
        hsm[tid + q * 256] = 0.f;
    __syncthreads();

    for (int step = 0; step < maxlen; step++) {
        const int t = d ? (maxlen - 1 - step) : step;

        // accumulators: 8 word-pairs x 3 gates, packed fp32x2
        u64 accr[WPB / 2], accz[WPB / 2], accn[WPB / 2];
#pragma unroll
        for (int p = 0; p < WPB / 2; p++) { accr[p] = 0ull; accz[p] = 0ull; accn[p] = 0ull; }

        // ---- gh = h @ W_hh^T; 4 k per iter, weights prefetched (R3 loop) ---
        float cur[12], nxt[12];
        {
            const float* __restrict__ w0 = Wt + tid;
#pragma unroll
            for (int i = 0; i < 4; i++) {
                cur[3 * i + 0] = __ldg(w0 + (size_t)i * G3);
                cur[3 * i + 1] = __ldg(w0 + (size_t)i * G3 + 256);
                cur[3 * i + 2] = __ldg(w0 + (size_t)i * G3 + 512);
            }
        }
#pragma unroll 2
        for (int kg = 0; kg < HH / 4; kg++) {
            const int kn = (kg + 1 < HH / 4) ? (kg + 1) : kg;
            const float* __restrict__ wN = Wt + (size_t)(4 * kn) * G3 + tid;
#pragma unroll
            for (int i = 0; i < 4; i++) {
                nxt[3 * i + 0] = __ldg(wN + (size_t)i * G3);
                nxt[3 * i + 1] = __ldg(wN + (size_t)i * G3 + 256);
                nxt[3 * i + 2] = __ldg(wN + (size_t)i * G3 + 512);
            }
#pragma unroll
            for (int i = 0; i < 4; i++) {
                const int k = 4 * kg + i;
                const u64 wr2 = dup2(cur[3 * i + 0]);
                const u64 wz2 = dup2(cur[3 * i + 1]);
                const u64 wn2 = dup2(cur[3 * i + 2]);
                const ulonglong2* __restrict__ hk =
                    reinterpret_cast<const ulonglong2*>(&hsm[k * HROW]);
#pragma unroll
                for (int q = 0; q < WPB / 4; q++) {      // 4 LDS.128 broadcast
                    ulonglong2 a = hk[q];                // words 4q..4q+3
                    fma2(accr[2 * q],     a.x, wr2);
                    fma2(accz[2 * q],     a.x, wz2);
                    fma2(accn[2 * q],     a.x, wn2);
                    fma2(accr[2 * q + 1], a.y, wr2);
                    fma2(accz[2 * q + 1], a.y, wz2);
                    fma2(accn[2 * q + 1], a.y, wn2);
                }
            }
#pragma unroll
            for (int i = 0; i < 12; i++) cur[i] = nxt[i];
        }

        // ---- gates (thread-local), update h --------------------------------
        __syncthreads();                                 // all h reads done
        const float* ar = reinterpret_cast<const float*>(accr);
        const float* az = reinterpret_cast<const float*>(accz);
        const float* an = reinterpret_cast<const float*>(accn);
#pragma unroll
        for (int w = 0; w < WPB; w++) {
            const int n  = wid_s[w];
            const int ch = chars[n * CC + t];
            const int mk = chars_mask[n * CC + t];
            const float* __restrict__ Prow = &g_P[d][ch][0];
            float xr = Prow[tid];                        // b_ih + b_hh folded
            float xz = Prow[tid + 256];
            float xn = Prow[tid + 512];                  // b_ih only
            float hold = hsm[tid * HROW + w];
            float r  = sigmoid_f(xr + ar[w]);
            float z  = sigmoid_f(xz + az[w]);
            float hn = bn + an[w];
            float nn = tanh_f(fmaf(r, hn, xn));
            float hnew = (1.f - z) * nn + z * hold;
            hsm[tid * HROW + w] = mk ? hnew : hold;      // freeze past seq end
        }
        __syncthreads();                                 // h visible next step
    }

    // ---- final write: out[n, d*256 + i] = h * data_mask[n] -----------------
#pragma unroll
    for (int w = 0; w < WPB; w++) {
        const int n = wid_s[w];
        const float dm = data_mask[n] ? 1.f : 0.f;
        out[(size_t)n * 512 + d * 256 + tid] = hsm[tid * HROW + w] * dm;
    }
}

// ---------------------------------------------------------------------------
extern "C" void kernel_launch(void* const* d_in, const int* in_sizes, int n_in,
                              void* d_out, int out_size)
{
    const int*   chars      = (const int*)  d_in[0];
    const int*   chars_mask = (const int*)  d_in[1];
    const int*   data_mask  = (const int*)  d_in[2];
    const float* embed      = (const float*)d_in[3];
    const float* Wih_fw     = (const float*)d_in[4];
    const float* Whh_fw     = (const float*)d_in[5];
    const float* bih_fw     = (const float*)d_in[6];
    const float* bhh_fw     = (const float*)d_in[7];
    const float* Wih_bw     = (const float*)d_in[8];
    const float* Whh_bw     = (const float*)d_in[9];
    const float* bih_bw     = (const float*)d_in[10];
    const float* bhh_bw     = (const float*)d_in[11];
    float* out = (float*)d_out;

    prep_tr_kernel<<<dim3(G3, 2), HH>>>(Whh_fw, Whh_bw, Wih_fw, Wih_bw);
    prep_p_kernel<<<dim3(NV, 2), 256>>>(embed, bih_fw, bhh_fw, bih_bw, bhh_bw);
    prep_sort_kernel<<<1, 1024>>>(chars_mask);
    gru_kernel<<<dim3(NTILES, 2), 256>>>(chars, chars_mask, data_mask,
                                         bhh_fw, bhh_bw, out);
}